// round 4
// baseline (speedup 1.0000x reference)
#include <cuda_runtime.h>

// WKV7 (RWKV-7) recurrence, T=4096, H=32, N=64.
//
// v2 design: 16 lanes per state row (each lane owns a float4 of 4 state
// elements), 2 rows per warp -> 1024 warps total. Per step:
//   p = s . a_t           (in-lane dot4, then 4-level shfl_xor butterfly)
//   s = s*w + v_i*k + p*b
//   q = s . r_t           (in-lane dot4; its butterfly runs during the NEXT
//                          step, manually interleaved with that step's
//                          p-butterfly for 2-way ILP through shfl latency)
// Inputs for t+1 are prefetched while computing step t.

#define TT 4096
#define HH 32
#define NN 64
#define CC (HH * NN)  // 2048 channels per timestep

__device__ __forceinline__ float dot4(float4 x, float4 y) {
    return fmaf(x.x, y.x, x.y * y.y) + fmaf(x.z, y.z, x.w * y.w);
}

__global__ __launch_bounds__(128) void wkv7_scan_kernel(
    const float* __restrict__ r, const float* __restrict__ w,
    const float* __restrict__ k, const float* __restrict__ v,
    const float* __restrict__ a, const float* __restrict__ b,
    const float* __restrict__ s0, float* __restrict__ out)
{
    const int warp = (blockIdx.x * blockDim.x + threadIdx.x) >> 5;  // 0..1023
    const int lane = threadIdx.x & 31;
    const int h    = warp >> 5;          // 32 warps per head
    const int wh   = warp & 31;
    const int half = lane >> 4;          // which of the warp's 2 rows
    const int g    = lane & 15;          // position within the row's 16 lanes
    const int i    = (wh << 1) + half;   // row index within head (0..63)
    const int j0   = g << 2;             // first of this lane's 4 j-columns

    // Initial state row chunk: s0[h, i, j0..j0+3]
    float4 s = *reinterpret_cast<const float4*>(
        s0 + ((size_t)(h * NN + i) * NN + j0));

    const int vecbase = h * NN + j0;   // offset of this lane's float4 in a [C] vector
    const int vibase  = h * NN + i;    // offset of v_i / y_i in a [C] vector

    // Prefetch t = 0
    float4 A = *reinterpret_cast<const float4*>(a + vecbase);
    float4 W = *reinterpret_cast<const float4*>(w + vecbase);
    float4 K = *reinterpret_cast<const float4*>(k + vecbase);
    float4 B = *reinterpret_cast<const float4*>(b + vecbase);
    float4 R = *reinterpret_cast<const float4*>(r + vecbase);
    float  V = v[vibase];

    float q = 0.0f;   // carried y-partial from the previous step (none yet)

    #pragma unroll 1
    for (int t = 0; t < TT; ++t) {
        // ---- prefetch t+1 (clamped; last-step reload is harmless)
        const int tn = (t + 1 < TT) ? (t + 1) : t;
        const size_t noff = (size_t)tn * CC + vecbase;
        float4 An = *reinterpret_cast<const float4*>(a + noff);
        float4 Wn = *reinterpret_cast<const float4*>(w + noff);
        float4 Kn = *reinterpret_cast<const float4*>(k + noff);
        float4 Bn = *reinterpret_cast<const float4*>(b + noff);
        float4 Rn = *reinterpret_cast<const float4*>(r + noff);
        float  Vn = v[(size_t)tn * CC + vibase];

        // ---- sa partial for step t (uses state BEFORE update)
        float p = dot4(s, A);

        // ---- two interleaved 4-level butterflies (width 16):
        //      p (this step's sa) and q (previous step's y) are independent.
        float ps, qs;
        ps = __shfl_xor_sync(0xffffffffu, p, 8);
        qs = __shfl_xor_sync(0xffffffffu, q, 8);
        p += ps;  q += qs;
        ps = __shfl_xor_sync(0xffffffffu, p, 4);
        qs = __shfl_xor_sync(0xffffffffu, q, 4);
        p += ps;  q += qs;
        ps = __shfl_xor_sync(0xffffffffu, p, 2);
        qs = __shfl_xor_sync(0xffffffffu, q, 2);
        p += ps;  q += qs;
        ps = __shfl_xor_sync(0xffffffffu, p, 1);
        qs = __shfl_xor_sync(0xffffffffu, q, 1);
        p += ps;  q += qs;

        // ---- emit y for step t-1
        if (g == 0 && t > 0) {
            out[(size_t)(t - 1) * CC + vibase] = q;
        }

        // ---- state update: s = s*w + v_i*k + sa*b
        s.x = fmaf(p, B.x, fmaf(V, K.x, s.x * W.x));
        s.y = fmaf(p, B.y, fmaf(V, K.y, s.y * W.y));
        s.z = fmaf(p, B.z, fmaf(V, K.z, s.z * W.z));
        s.w = fmaf(p, B.w, fmaf(V, K.w, s.w * W.w));

        // ---- y partial for step t (reduced during step t+1)
        q = dot4(s, R);

        // rotate prefetch buffers
        A = An; W = Wn; K = Kn; B = Bn; R = Rn; V = Vn;
    }

    // ---- final y reduction (step T-1)
    q += __shfl_xor_sync(0xffffffffu, q, 8);
    q += __shfl_xor_sync(0xffffffffu, q, 4);
    q += __shfl_xor_sync(0xffffffffu, q, 2);
    q += __shfl_xor_sync(0xffffffffu, q, 1);
    if (g == 0) {
        out[(size_t)(TT - 1) * CC + vibase] = q;
    }

    // ---- final state: out[T*C + (h*N + i)*N + j0 ..]
    *reinterpret_cast<float4*>(out + (size_t)TT * CC +
                               ((size_t)(h * NN + i) * NN + j0)) = s;
}

// Input order (metadata): seq_length(int32), r, w, k, v, a, b, state2.
// Output: concat(x[T,H,1,N], state2_out[H,N,N]) as float32.
extern "C" void kernel_launch(void* const* d_in, const int* in_sizes, int n_in,
                              void* d_out, int out_size)
{
    const float* r  = (const float*)d_in[1];
    const float* w  = (const float*)d_in[2];
    const float* k  = (const float*)d_in[3];
    const float* v  = (const float*)d_in[4];
    const float* a  = (const float*)d_in[5];
    const float* b  = (const float*)d_in[6];
    const float* s0 = (const float*)d_in[7];
    float* out = (float*)d_out;

    // 1024 warps -> 256 blocks of 128 threads
    wkv7_scan_kernel<<<256, 128>>>(r, w, k, v, a, b, s0, out);
}

// round 5
// speedup vs baseline: 1.1066x; 1.1066x over previous
#include <cuda_runtime.h>

// WKV7 (RWKV-7) recurrence, T=4096, H=32, N=64.
//
// v3: warp-per-row (max concurrency: 2048 warps, like v1), but the two
// per-step warp reductions are software-pipelined: the butterfly for
// y_{t-1} (q) runs interleaved with the butterfly for sa_t (p), so the
// serial shfl depth per step is 5 instead of 10.
//   p = s_{t-1} . a_t      (dot2 + 5-level shfl_xor, interleaved with q)
//   q = s_{t-1} . r_{t-1}  (partial from previous step, reduced now)
//   s = s*w + v_i*k + p*b
//   q' = s . r_t           (reduced during next step)
// Inputs for t+1 are prefetched while computing step t.

#define TT 4096
#define HH 32
#define NN 64
#define CC (HH * NN)  // 2048 channels per timestep

__global__ __launch_bounds__(32) void wkv7_scan_kernel(
    const float* __restrict__ r, const float* __restrict__ w,
    const float* __restrict__ k, const float* __restrict__ v,
    const float* __restrict__ a, const float* __restrict__ b,
    const float* __restrict__ s0, float* __restrict__ out)
{
    const int row  = blockIdx.x;        // 0..2047 == h*64 + i
    const int h    = row >> 6;
    const int i    = row & 63;
    const int lane = threadIdx.x;       // 0..31
    const int j0   = lane << 1;

    // Initial state row: s0[h, i, j0], s0[h, i, j0+1]
    float2 s = *reinterpret_cast<const float2*>(
        s0 + ((size_t)(h * NN + i) * NN + j0));

    const int vecbase = h * NN + j0;    // this lane's float2 within a [C] vector
    const int vibase  = h * NN + i;     // v_i / y_i within a [C] vector

    // Prefetch t = 0
    float2 A = *reinterpret_cast<const float2*>(a + vecbase);
    float2 W = *reinterpret_cast<const float2*>(w + vecbase);
    float2 K = *reinterpret_cast<const float2*>(k + vecbase);
    float2 B = *reinterpret_cast<const float2*>(b + vecbase);
    float2 R = *reinterpret_cast<const float2*>(r + vecbase);
    float  V = v[vibase];

    float q = 0.0f;  // pending y-partial from previous step

    #pragma unroll 1
    for (int t = 0; t < TT; ++t) {
        // ---- prefetch t+1 (clamped; last-step reload harmless)
        const int tn = (t + 1 < TT) ? (t + 1) : t;
        const size_t noff = (size_t)tn * CC;
        float2 An = *reinterpret_cast<const float2*>(a + noff + vecbase);
        float2 Wn = *reinterpret_cast<const float2*>(w + noff + vecbase);
        float2 Kn = *reinterpret_cast<const float2*>(k + noff + vecbase);
        float2 Bn = *reinterpret_cast<const float2*>(b + noff + vecbase);
        float2 Rn = *reinterpret_cast<const float2*>(r + noff + vecbase);
        float  Vn = v[noff + vibase];

        // ---- sa partial for step t (state BEFORE update)
        float p = fmaf(s.x, A.x, s.y * A.y);

        // ---- two interleaved 5-level butterflies:
        //      p (this step's sa) and q (previous step's y) are independent.
        float ps, qs;
        ps = __shfl_xor_sync(0xffffffffu, p, 16);
        qs = __shfl_xor_sync(0xffffffffu, q, 16);
        p += ps;  q += qs;
        ps = __shfl_xor_sync(0xffffffffu, p, 8);
        qs = __shfl_xor_sync(0xffffffffu, q, 8);
        p += ps;  q += qs;
        ps = __shfl_xor_sync(0xffffffffu, p, 4);
        qs = __shfl_xor_sync(0xffffffffu, q, 4);
        p += ps;  q += qs;
        ps = __shfl_xor_sync(0xffffffffu, p, 2);
        qs = __shfl_xor_sync(0xffffffffu, q, 2);
        p += ps;  q += qs;
        ps = __shfl_xor_sync(0xffffffffu, p, 1);
        qs = __shfl_xor_sync(0xffffffffu, q, 1);
        p += ps;  q += qs;

        // ---- emit y for step t-1
        if (lane == 0 && t > 0) {
            out[(size_t)(t - 1) * CC + vibase] = q;
        }

        // ---- state update: s = s*w + v_i*k + sa*b
        s.x = fmaf(p, B.x, fmaf(V, K.x, s.x * W.x));
        s.y = fmaf(p, B.y, fmaf(V, K.y, s.y * W.y));

        // ---- y partial for step t (reduced during step t+1)
        q = fmaf(s.x, R.x, s.y * R.y);

        // rotate prefetch buffers
        A = An; W = Wn; K = Kn; B = Bn; R = Rn; V = Vn;
    }

    // ---- final y reduction (step T-1)
    q += __shfl_xor_sync(0xffffffffu, q, 16);
    q += __shfl_xor_sync(0xffffffffu, q, 8);
    q += __shfl_xor_sync(0xffffffffu, q, 4);
    q += __shfl_xor_sync(0xffffffffu, q, 2);
    q += __shfl_xor_sync(0xffffffffu, q, 1);
    if (lane == 0) {
        out[(size_t)(TT - 1) * CC + vibase] = q;
    }

    // ---- final state
    *reinterpret_cast<float2*>(out + (size_t)TT * CC +
                               ((size_t)(h * NN + i) * NN + j0)) = s;
}

// Input order (metadata): seq_length(int32), r, w, k, v, a, b, state2.
// Output: concat(x[T,H,1,N], state2_out[H,N,N]) as float32.
extern "C" void kernel_launch(void* const* d_in, const int* in_sizes, int n_in,
                              void* d_out, int out_size)
{
    const float* r  = (const float*)d_in[1];
    const float* w  = (const float*)d_in[2];
    const float* k  = (const float*)d_in[3];
    const float* v  = (const float*)d_in[4];
    const float* a  = (const float*)d_in[5];
    const float* b  = (const float*)d_in[6];
    const float* s0 = (const float*)d_in[7];
    float* out = (float*)d_out;

    wkv7_scan_kernel<<<HH * NN, 32>>>(r, w, k, v, a, b, s0, out);
}

// round 6
// speedup vs baseline: 1.4013x; 1.2663x over previous
#include <cuda_runtime.h>

// WKV7 (RWKV-7) recurrence, T=4096, H=32, N=64.
//
// v4: warp-per-row (2048 warps) with
//  - 128-thread CTAs holding 4 rows of the SAME head, so the per-step
//    vector loads (r,w,k,a,b) of the 4 warps hit the same L1 lines;
//  - prefetch distance 2 via 4 rotating register buffers (unroll 4, no
//    register moves) so even L2-latency first-touch misses are covered;
//  - the two per-step warp reductions software-pipelined (y_{t-1} butterfly
//    interleaved with sa_t butterfly for 2-way ILP through shfl latency).

#define TT 4096
#define HH 32
#define NN 64
#define CC (HH * NN)  // 2048 channels per timestep

__global__ __launch_bounds__(128) void wkv7_scan_kernel(
    const float* __restrict__ r, const float* __restrict__ w,
    const float* __restrict__ k, const float* __restrict__ v,
    const float* __restrict__ a, const float* __restrict__ b,
    const float* __restrict__ s0, float* __restrict__ out)
{
    const int cta  = blockIdx.x;          // 0..511
    const int h    = cta >> 4;            // 16 CTAs per head
    const int wid  = threadIdx.x >> 5;    // 0..3 (row within CTA)
    const int lane = threadIdx.x & 31;
    const int i    = ((cta & 15) << 2) + wid;   // row in head, 0..63
    const int j0   = lane << 1;

    // Initial state row: s0[h, i, j0..j0+1]
    float2 s = *reinterpret_cast<const float2*>(
        s0 + ((size_t)(h * NN + i) * NN + j0));

    const int vecbase = h * NN + j0;   // this lane's float2 within a [C] vector
    const int vibase  = h * NN + i;    // v_i / y_i within a [C] vector

    // 4 rotating prefetch buffers; slot t&3 holds step t's inputs.
    float2 Ab[4], Wb[4], Kb[4], Bb[4], Rb[4];
    float  Vb[4];

    // Preload t = 0 and t = 1
    #pragma unroll
    for (int sl = 0; sl < 2; ++sl) {
        const size_t off = (size_t)sl * CC;
        Ab[sl] = *reinterpret_cast<const float2*>(a + off + vecbase);
        Wb[sl] = *reinterpret_cast<const float2*>(w + off + vecbase);
        Kb[sl] = *reinterpret_cast<const float2*>(k + off + vecbase);
        Bb[sl] = *reinterpret_cast<const float2*>(b + off + vecbase);
        Rb[sl] = *reinterpret_cast<const float2*>(r + off + vecbase);
        Vb[sl] = v[off + vibase];
    }

    float q = 0.0f;  // pending y-partial from previous step

    #pragma unroll 4
    for (int t = 0; t < TT; ++t) {
        // ---- prefetch t+2 into slot (t+2)&3 (clamped; tail reload harmless)
        {
            const int tn = (t + 2 < TT) ? (t + 2) : (TT - 1);
            const int sl = (t + 2) & 3;
            const size_t off = (size_t)tn * CC;
            Ab[sl] = *reinterpret_cast<const float2*>(a + off + vecbase);
            Wb[sl] = *reinterpret_cast<const float2*>(w + off + vecbase);
            Kb[sl] = *reinterpret_cast<const float2*>(k + off + vecbase);
            Bb[sl] = *reinterpret_cast<const float2*>(b + off + vecbase);
            Rb[sl] = *reinterpret_cast<const float2*>(r + off + vecbase);
            Vb[sl] = v[off + vibase];
        }

        const int cu = t & 3;
        const float2 A = Ab[cu], W = Wb[cu], K = Kb[cu],
                     Bv = Bb[cu], R = Rb[cu];
        const float  V = Vb[cu];

        // ---- sa partial for step t (state BEFORE update)
        float p = fmaf(s.x, A.x, s.y * A.y);

        // ---- two interleaved 5-level butterflies:
        //      p (this step's sa) and q (previous step's y) are independent.
        float ps, qs;
        ps = __shfl_xor_sync(0xffffffffu, p, 16);
        qs = __shfl_xor_sync(0xffffffffu, q, 16);
        p += ps;  q += qs;
        ps = __shfl_xor_sync(0xffffffffu, p, 8);
        qs = __shfl_xor_sync(0xffffffffu, q, 8);
        p += ps;  q += qs;
        ps = __shfl_xor_sync(0xffffffffu, p, 4);
        qs = __shfl_xor_sync(0xffffffffu, q, 4);
        p += ps;  q += qs;
        ps = __shfl_xor_sync(0xffffffffu, p, 2);
        qs = __shfl_xor_sync(0xffffffffu, q, 2);
        p += ps;  q += qs;
        ps = __shfl_xor_sync(0xffffffffu, p, 1);
        qs = __shfl_xor_sync(0xffffffffu, q, 1);
        p += ps;  q += qs;

        // ---- emit y for step t-1
        if (lane == 0 && t > 0) {
            out[(size_t)(t - 1) * CC + vibase] = q;
        }

        // ---- state update: s = s*w + v_i*k + sa*b
        s.x = fmaf(p, Bv.x, fmaf(V, K.x, s.x * W.x));
        s.y = fmaf(p, Bv.y, fmaf(V, K.y, s.y * W.y));

        // ---- y partial for step t (reduced during step t+1)
        q = fmaf(s.x, R.x, s.y * R.y);
    }

    // ---- final y reduction (step T-1)
    q += __shfl_xor_sync(0xffffffffu, q, 16);
    q += __shfl_xor_sync(0xffffffffu, q, 8);
    q += __shfl_xor_sync(0xffffffffu, q, 4);
    q += __shfl_xor_sync(0xffffffffu, q, 2);
    q += __shfl_xor_sync(0xffffffffu, q, 1);
    if (lane == 0) {
        out[(size_t)(TT - 1) * CC + vibase] = q;
    }

    // ---- final state
    *reinterpret_cast<float2*>(out + (size_t)TT * CC +
                               ((size_t)(h * NN + i) * NN + j0)) = s;
}

// Input order (metadata): seq_length(int32), r, w, k, v, a, b, state2.
// Output: concat(x[T,H,1,N], state2_out[H,N,N]) as float32.
extern "C" void kernel_launch(void* const* d_in, const int* in_sizes, int n_in,
                              void* d_out, int out_size)
{
    const float* r  = (const float*)d_in[1];
    const float* w  = (const float*)d_in[2];
    const float* k  = (const float*)d_in[3];
    const float* v  = (const float*)d_in[4];
    const float* a  = (const float*)d_in[5];
    const float* b  = (const float*)d_in[6];
    const float* s0 = (const float*)d_in[7];
    float* out = (float*)d_out;

    // 512 CTAs x 128 threads = 2048 warps (one per state row)
    wkv7_scan_kernel<<<512, 128>>>(r, w, k, v, a, b, s0, out);
}

// round 9
// speedup vs baseline: 1.8559x; 1.3244x over previous
#include <cuda_runtime.h>

// WKV7 (RWKV-7) recurrence, T=4096, H=32, N=64.
//
// v5: warp-per-row (2048 warps), 256-thread CTAs = 8 rows of the SAME head.
// Per-step vectors (r,w,k,a,b) are staged into a 32-deep shared-memory ring
// by cp.async, issued 3 sync-periods (24 steps) ahead of consumption, so no
// global-memory latency ever sits on the recurrence's serial path.
// Consumers read vectors with LDS (prefetched 1 step ahead into registers).
// The two per-step warp reductions stay software-pipelined (y_{t-1} butterfly
// interleaved with sa_t butterfly).

#define TT 4096
#define HH 32
#define NN 64
#define CC (HH * NN)       // 2048 channels per timestep

#define SP 8               // steps per sync period
#define NGRP 4             // periods resident in the ring
#define STAGES (SP * NGRP) // 32
#define SFLOATS 320        // 5 vectors x 64 floats per stage

__device__ __forceinline__ void cp16(float* dst_smem, const float* src) {
    unsigned int d = (unsigned int)__cvta_generic_to_shared(dst_smem);
    asm volatile("cp.async.ca.shared.global [%0], [%1], 16;\n"
                 :: "r"(d), "l"(src));
}
__device__ __forceinline__ void cp_commit() {
    asm volatile("cp.async.commit_group;\n");
}
template <int NMAX>
__device__ __forceinline__ void cp_wait() {
    asm volatile("cp.async.wait_group %0;\n" :: "n"(NMAX));
}

__global__ __launch_bounds__(256) void wkv7_scan_kernel(
    const float* __restrict__ r, const float* __restrict__ w,
    const float* __restrict__ k, const float* __restrict__ v,
    const float* __restrict__ a, const float* __restrict__ b,
    const float* __restrict__ s0, float* __restrict__ out)
{
    __shared__ float stage[STAGES][SFLOATS];  // 40 KB

    const int tid  = threadIdx.x;
    const int cta  = blockIdx.x;          // 0..255
    const int h    = cta >> 3;            // 8 CTAs per head
    const int wid  = tid >> 5;            // 0..7
    const int lane = tid & 31;
    const int i    = ((cta & 7) << 3) + wid;  // row in head, 0..63
    const int j0   = lane << 1;

    // ---- producer setup: threads 0..79 each own one 16B chunk per stage
    const int pvec  = tid >> 4;           // 0..4 (only used when tid<80)
    const int pquad = tid & 15;           // 0..15
    const float* psrc = nullptr;
    if (tid < 80) {
        const float* bases[5] = {r, w, k, a, b};
        psrc = bases[pvec] + h * NN + pquad * 4;
    }

    // issue one sync-period worth of stages for steps [tbase, tbase+SP)
    auto issue_period = [&](int tbase) {
        if (tid < 80) {
            #pragma unroll
            for (int u = 0; u < SP; ++u) {
                int t    = tbase + u;
                int tc   = (t < TT) ? t : (TT - 1);
                int slot = t & (STAGES - 1);
                cp16(&stage[slot][pvec * 64 + pquad * 4],
                     psrc + (size_t)tc * CC);
            }
        }
        cp_commit();   // uniform: empty group for non-producers is harmless
    };

    // ---- initial state row
    float2 s = *reinterpret_cast<const float2*>(
        s0 + ((size_t)(h * NN + i) * NN + j0));

    const int vibase = h * NN + i;        // v_i / y_i within a [C] vector

    // ---- v scalar: distance-2 register rotation
    float Vb[4];
    Vb[0] = v[vibase];
    Vb[1] = v[(size_t)CC + vibase];

    // ---- prologue: fill periods 0,1,2
    issue_period(0 * SP);
    issue_period(1 * SP);
    issue_period(2 * SP);
    cp_wait<1>();          // periods 0,1 complete
    __syncthreads();       // make them visible to all threads

    // ---- prefetch step-0 vectors from smem
    float2 A  = *reinterpret_cast<const float2*>(&stage[0][  0 + j0]);
    float2 W  = *reinterpret_cast<const float2*>(&stage[0][ 64 + j0]);
    float2 K  = *reinterpret_cast<const float2*>(&stage[0][128 + j0]);
    float2 Av = *reinterpret_cast<const float2*>(&stage[0][192 + j0]); // 'a'
    float2 Bv = *reinterpret_cast<const float2*>(&stage[0][256 + j0]); // 'b'

    float q = 0.0f;  // pending y-partial from previous step

    const int NHALF = TT / SP;            // 512 sync periods
    for (int hb = 0; hb < NHALF; ++hb) {
        __syncthreads();                  // everyone done with period hb-1
        issue_period((hb + 3) * SP);      // refill the stages of period hb-1
        cp_wait<2>();                     // period hb+1 now complete
        __syncthreads();                  // visibility of period hb(+1)

        const int tbase = hb * SP;
        #pragma unroll
        for (int u = 0; u < SP; ++u) {
            const int t  = tbase + u;
            const int sn = (t + 1) & (STAGES - 1);  // next step's stage

            // ---- prefetch t+1 vectors from smem (last one is dummy-read)
            float2 An = *reinterpret_cast<const float2*>(&stage[sn][  0 + j0]);
            float2 Wn = *reinterpret_cast<const float2*>(&stage[sn][ 64 + j0]);
            float2 Kn = *reinterpret_cast<const float2*>(&stage[sn][128 + j0]);
            float2 an = *reinterpret_cast<const float2*>(&stage[sn][192 + j0]);
            float2 bn = *reinterpret_cast<const float2*>(&stage[sn][256 + j0]);

            // ---- prefetch v for t+2
            {
                const int tv = (t + 2 < TT) ? (t + 2) : (TT - 1);
                Vb[(t + 2) & 3] = v[(size_t)tv * CC + vibase];
            }
            const float V = Vb[t & 3];

            // ---- sa partial for step t (state BEFORE update); r-vec is W?? no:
            // naming: A=r-vec? No: A holds r? (see loads: A<-stage[..][0]=r)
            // 'Av' is the a-vector, 'A' is the r-vector. Dot uses a-vector:
            float p = fmaf(s.x, Av.x, s.y * Av.y);

            // ---- interleaved 5-level butterflies: p (sa_t) and q (y_{t-1})
            float ps, qs;
            ps = __shfl_xor_sync(0xffffffffu, p, 16);
            qs = __shfl_xor_sync(0xffffffffu, q, 16);
            p += ps;  q += qs;
            ps = __shfl_xor_sync(0xffffffffu, p, 8);
            qs = __shfl_xor_sync(0xffffffffu, q, 8);
            p += ps;  q += qs;
            ps = __shfl_xor_sync(0xffffffffu, p, 4);
            qs = __shfl_xor_sync(0xffffffffu, q, 4);
            p += ps;  q += qs;
            ps = __shfl_xor_sync(0xffffffffu, p, 2);
            qs = __shfl_xor_sync(0xffffffffu, q, 2);
            p += ps;  q += qs;
            ps = __shfl_xor_sync(0xffffffffu, p, 1);
            qs = __shfl_xor_sync(0xffffffffu, q, 1);
            p += ps;  q += qs;

            // ---- emit y for step t-1
            if (lane == 0 && t > 0) {
                out[(size_t)(t - 1) * CC + vibase] = q;
            }

            // ---- state update: s = s*w + v_i*k + sa*b
            s.x = fmaf(p, Bv.x, fmaf(V, K.x, s.x * W.x));
            s.y = fmaf(p, Bv.y, fmaf(V, K.y, s.y * W.y));

            // ---- y partial for step t (A = r-vector), reduced next step
            q = fmaf(s.x, A.x, s.y * A.y);

            // rotate
            A = An; W = Wn; K = Kn; Av = an; Bv = bn;
        }
    }

    // ---- final y reduction (step T-1)
    q += __shfl_xor_sync(0xffffffffu, q, 16);
    q += __shfl_xor_sync(0xffffffffu, q, 8);
    q += __shfl_xor_sync(0xffffffffu, q, 4);
    q += __shfl_xor_sync(0xffffffffu, q, 2);
    q += __shfl_xor_sync(0xffffffffu, q, 1);
    if (lane == 0) {
        out[(size_t)(TT - 1) * CC + vibase] = q;
    }

    // ---- final state
    *reinterpret_cast<float2*>(out + (size_t)TT * CC +
                               ((size_t)(h * NN + i) * NN + j0)) = s;
}

// Input order (metadata): seq_length(int32), r, w, k, v, a, b, state2.
// Output: concat(x[T,H,1,N], state2_out[H,N,N]) as float32.
extern "C" void kernel_launch(void* const* d_in, const int* in_sizes, int n_in,
                              void* d_out, int out_size)
{
    const float* r  = (const float*)d_in[1];
    const float* w  = (const float*)d_in[2];
    const float* k  = (const float*)d_in[3];
    const float* v  = (const float*)d_in[4];
    const float* a  = (const float*)d_in[5];
    const float* b  = (const float*)d_in[6];
    const float* s0 = (const float*)d_in[7];
    float* out = (float*)d_out;

    // 256 CTAs x 256 threads = 2048 warps (one per state row)
    wkv7_scan_kernel<<<256, 256>>>(r, w, k, v, a, b, s0, out);
}

// round 14
// speedup vs baseline: 4.5036x; 2.4266x over previous
#include <cuda_runtime.h>

// WKV7 (RWKV-7) recurrence, T=4096, H=32, N=64.
//
// v7 = v5's cp.async shared-memory ring staging + 16-lane rows:
// each lane owns a float4 of the state row, 2 rows per warp, 1024 warps.
// Butterflies are 4 levels (vs 5) and every MIO op serves 2 rows.
// All per-step inputs (r,w,k,a,b,v) come from the smem ring; no global
// loads on the consumer path. y_{t-1} reduction is interleaved with the
// sa_t reduction (2-way ILP through shfl latency).

#define TT 4096
#define HH 32
#define NN 64
#define CC (HH * NN)       // 2048 channels per timestep

#define SP 8               // steps per sync period
#define NGRP 4             // periods resident in the ring
#define STAGES (SP * NGRP) // 32
#define SFLOATS 384        // 6 vectors x 64 floats per stage

__device__ __forceinline__ void cp16(float* dst_smem, const float* src) {
    unsigned int d = (unsigned int)__cvta_generic_to_shared(dst_smem);
    asm volatile("cp.async.ca.shared.global [%0], [%1], 16;\n"
                 :: "r"(d), "l"(src));
}
__device__ __forceinline__ void cp_commit() {
    asm volatile("cp.async.commit_group;\n");
}
template <int NMAX>
__device__ __forceinline__ void cp_wait() {
    asm volatile("cp.async.wait_group %0;\n" :: "n"(NMAX));
}
__device__ __forceinline__ float dot4(float4 x, float4 y) {
    return fmaf(x.x, y.x, x.y * y.y) + fmaf(x.z, y.z, x.w * y.w);
}

__global__ __launch_bounds__(128) void wkv7_scan_kernel(
    const float* __restrict__ r, const float* __restrict__ w,
    const float* __restrict__ k, const float* __restrict__ v,
    const float* __restrict__ a, const float* __restrict__ b,
    const float* __restrict__ s0, float* __restrict__ out)
{
    __shared__ float stage[STAGES][SFLOATS];  // 48 KB

    const int tid  = threadIdx.x;
    const int cta  = blockIdx.x;          // 0..255
    const int h    = cta >> 3;            // 8 CTAs per head
    const int wid  = tid >> 5;            // 0..3
    const int lane = tid & 31;
    const int half = lane >> 4;           // which of the warp's 2 rows
    const int g    = lane & 15;           // lane within the row group
    const int i    = ((cta & 7) << 3) + (wid << 1) + half;  // row 0..63
    const int j0   = g << 2;              // this lane's 4 j-columns

    // ---- producer setup: threads 0..95 each own one 16B chunk per stage
    //      vector order in a stage: r | w | k | a | b | v   (64 floats each)
    const int pvec  = tid >> 4;           // 0..5 (used when tid<96)
    const int pquad = tid & 15;           // 0..15
    const float* psrc = nullptr;
    if (tid < 96) {
        const float* bases[6] = {r, w, k, a, b, v};
        psrc = bases[pvec] + h * NN + pquad * 4;
    }

    auto issue_period = [&](int tbase) {
        if (tid < 96) {
            #pragma unroll
            for (int u = 0; u < SP; ++u) {
                int t    = tbase + u;
                int tc   = (t < TT) ? t : (TT - 1);
                int slot = t & (STAGES - 1);
                cp16(&stage[slot][pvec * 64 + pquad * 4],
                     psrc + (size_t)tc * CC);
            }
        }
        cp_commit();
    };

    // ---- initial state row chunk
    float4 s = *reinterpret_cast<const float4*>(
        s0 + ((size_t)(h * NN + i) * NN + j0));

    const int vibase = h * NN + i;        // v_i / y_i within a [C] vector

    // ---- prologue: fill periods 0,1,2
    issue_period(0 * SP);
    issue_period(1 * SP);
    issue_period(2 * SP);
    cp_wait<1>();
    __syncthreads();

    // ---- prefetch step-0 vectors from smem
    float4 Rv = *reinterpret_cast<const float4*>(&stage[0][  0 + j0]);
    float4 Wv = *reinterpret_cast<const float4*>(&stage[0][ 64 + j0]);
    float4 Kv = *reinterpret_cast<const float4*>(&stage[0][128 + j0]);
    float4 Av = *reinterpret_cast<const float4*>(&stage[0][192 + j0]);
    float4 Bv = *reinterpret_cast<const float4*>(&stage[0][256 + j0]);
    float  V  = stage[0][320 + i];

    float q = 0.0f;  // pending y-partial from previous step

    const int NPER = TT / SP;             // 512 sync periods
    for (int hb = 0; hb < NPER; ++hb) {
        __syncthreads();                  // everyone done with period hb-1
        issue_period((hb + 3) * SP);      // refill those stages
        cp_wait<2>();                     // period hb+1 complete
        __syncthreads();                  // visibility

        const int tbase = hb * SP;
        #pragma unroll
        for (int u = 0; u < SP; ++u) {
            const int t  = tbase + u;
            const int sn = (t + 1) & (STAGES - 1);  // next step's stage

            // ---- prefetch t+1 vectors from smem
            float4 Rn = *reinterpret_cast<const float4*>(&stage[sn][  0 + j0]);
            float4 Wn = *reinterpret_cast<const float4*>(&stage[sn][ 64 + j0]);
            float4 Kn = *reinterpret_cast<const float4*>(&stage[sn][128 + j0]);
            float4 an = *reinterpret_cast<const float4*>(&stage[sn][192 + j0]);
            float4 bn = *reinterpret_cast<const float4*>(&stage[sn][256 + j0]);
            float  Vn = stage[sn][320 + i];

            // ---- sa partial for step t (state BEFORE update)
            float p = dot4(s, Av);

            // ---- interleaved 4-level butterflies (width 16):
            //      p (sa_t) and q (y_{t-1}) are independent.
            float ps, qs;
            ps = __shfl_xor_sync(0xffffffffu, p, 8);
            qs = __shfl_xor_sync(0xffffffffu, q, 8);
            p += ps;  q += qs;
            ps = __shfl_xor_sync(0xffffffffu, p, 4);
            qs = __shfl_xor_sync(0xffffffffu, q, 4);
            p += ps;  q += qs;
            ps = __shfl_xor_sync(0xffffffffu, p, 2);
            qs = __shfl_xor_sync(0xffffffffu, q, 2);
            p += ps;  q += qs;
            ps = __shfl_xor_sync(0xffffffffu, p, 1);
            qs = __shfl_xor_sync(0xffffffffu, q, 1);
            p += ps;  q += qs;

            // ---- emit y for step t-1
            if (g == 0 && t > 0) {
                out[(size_t)(t - 1) * CC + vibase] = q;
            }

            // ---- state update: s = s*w + v_i*k + sa*b
            s.x = fmaf(p, Bv.x, fmaf(V, Kv.x, s.x * Wv.x));
            s.y = fmaf(p, Bv.y, fmaf(V, Kv.y, s.y * Wv.y));
            s.z = fmaf(p, Bv.z, fmaf(V, Kv.z, s.z * Wv.z));
            s.w = fmaf(p, Bv.w, fmaf(V, Kv.w, s.w * Wv.w));

            // ---- y partial for step t (reduced during step t+1)
            q = dot4(s, Rv);

            // rotate
            Rv = Rn; Wv = Wn; Kv = Kn; Av = an; Bv = bn; V = Vn;
        }
    }

    // ---- final y reduction (step T-1)
    q += __shfl_xor_sync(0xffffffffu, q, 8);
    q += __shfl_xor_sync(0xffffffffu, q, 4);
    q += __shfl_xor_sync(0xffffffffu, q, 2);
    q += __shfl_xor_sync(0xffffffffu, q, 1);
    if (g == 0) {
        out[(size_t)(TT - 1) * CC + vibase] = q;
    }

    // ---- final state
    *reinterpret_cast<float4*>(out + (size_t)TT * CC +
                               ((size_t)(h * NN + i) * NN + j0)) = s;
}

// Input order (metadata): seq_length(int32), r, w, k, v, a, b, state2.
// Output: concat(x[T,H,1,N], state2_out[H,N,N]) as float32.
extern "C" void kernel_launch(void* const* d_in, const int* in_sizes, int n_in,
                              void* d_out, int out_size)
{
    const float* r  = (const float*)d_in[1];
    const float* w  = (const float*)d_in[2];
    const float* k  = (const float*)d_in[3];
    const float* v  = (const float*)d_in[4];
    const float* a  = (const float*)d_in[5];
    const float* b  = (const float*)d_in[6];
    const float* s0 = (const float*)d_in[7];
    float* out = (float*)d_out;

    // 256 CTAs x 128 threads = 1024 warps (2 rows per warp)
    wkv7_scan_kernel<<<256, 128>>>(r, w, k, v, a, b, s0, out);
}